// round 2
// baseline (speedup 1.0000x reference)
#include <cuda_runtime.h>
#include <cuda_bf16.h>

// Direct 3x3 conv as implicit GEMM, fp32 FFMA baseline.
// Input  : [32, 128, 64, 64] fp32 (NCHW)
// Weights: [256, 128, 3, 3]  fp32 (OIHW)
// Output : [32, 256, 62, 62] fp32 (valid, stride 1)
//
// Block tile: 128 out-channels x (2 oh rows x 64 ow) for one image n.
// Grid: (31 oh-pairs, 32 images, 2 k-blocks) = 1984 blocks, 256 thr/block.
// Thread tile: 8 out-channels x 8 spatial columns (64 fp32 accumulators).
// K-loop: input channels in chunks of 8, all 9 taps per chunk.

__global__ __launch_bounds__(256, 2)
void conv3x3_kernel(const float* __restrict__ in,
                    const float* __restrict__ w,
                    float* __restrict__ out)
{
    // input tile: 8 channels x 4 rows x 64 cols (+4 pad -> 68 for bank spread)
    __shared__ float sIn[8][4][68];
    // weights transposed: 72 taps (8c x 9rs) x 128 out-channels
    __shared__ float sW[72][128];

    const int tid = threadIdx.x;
    const int tx  = tid & 15;   // spatial-column group
    const int ty  = tid >> 4;   // out-channel group
    const int oh0 = blockIdx.x * 2;
    const int n   = blockIdx.y;
    const int k0  = blockIdx.z * 128;

    const int oh_off  = tx >> 3;          // 0 or 1 (which oh row)
    const int ow_base = (tx & 7) * 8;     // 0..56

    float acc[8][8];
#pragma unroll
    for (int i = 0; i < 8; i++)
#pragma unroll
        for (int j = 0; j < 8; j++) acc[i][j] = 0.0f;

    const float* inN = in + n * 128 * 64 * 64;
    const int k_local = tid >> 1;   // 0..127
    const int half    = tid & 1;    // which 36-float half of the 72-tap row

    for (int c0 = 0; c0 < 128; c0 += 8) {
        // ---- stage input tile: 8c x 4rows x 64cols = 512 float4, 2 per thread
#pragma unroll
        for (int i = 0; i < 2; i++) {
            int idx  = tid + i * 256;       // float4 index
            int cc   = idx >> 6;            // 0..7
            int rem  = idx & 63;
            int row  = rem >> 4;            // 0..3
            int colf = (rem & 15) << 2;     // 0..60 step 4
            float4 v = *(const float4*)(inN + ((c0 + cc) * 64 + (oh0 + row)) * 64 + colf);
            *(float4*)&sIn[cc][row][colf] = v;
        }
        // ---- stage weights: 128k x 72 taps; each thread loads 36 contiguous
        const float* wp = w + (k0 + k_local) * 1152 + c0 * 9 + half * 36;
#pragma unroll
        for (int i = 0; i < 9; i++) {
            float4 v = *(const float4*)(wp + i * 4);
            int f = half * 36 + i * 4;
            sW[f + 0][k_local] = v.x;
            sW[f + 1][k_local] = v.y;
            sW[f + 2][k_local] = v.z;
            sW[f + 3][k_local] = v.w;
        }
        __syncthreads();

        // ---- compute: keep cc rolled (I-cache), unroll taps fully
#pragma unroll 1
        for (int cc = 0; cc < 8; cc++) {
#pragma unroll
            for (int r = 0; r < 3; r++) {
                const float* bp = &sIn[cc][oh_off + r][ow_base];
                float bb[12];
                *(float4*)&bb[0] = *(const float4*)(bp);
                *(float4*)&bb[4] = *(const float4*)(bp + 4);
                *(float4*)&bb[8] = *(const float4*)(bp + 8);
#pragma unroll
                for (int s = 0; s < 3; s++) {
                    const float* ap = &sW[cc * 9 + r * 3 + s][ty * 8];
                    float aa[8];
                    *(float4*)&aa[0] = *(const float4*)(ap);
                    *(float4*)&aa[4] = *(const float4*)(ap + 4);
#pragma unroll
                    for (int i = 0; i < 8; i++)
#pragma unroll
                        for (int j = 0; j < 8; j++)
                            acc[i][j] = fmaf(aa[i], bb[s + j], acc[i][j]);
                }
            }
        }
        __syncthreads();
    }

    // ---- epilogue: mask ow >= 62
    const int oh = oh0 + oh_off;
#pragma unroll
    for (int i = 0; i < 8; i++) {
        int k = k0 + ty * 8 + i;
        float* op = out + ((n * 256 + k) * 62 + oh) * 62 + ow_base;
#pragma unroll
        for (int j = 0; j < 8; j++) {
            if (ow_base + j < 62) op[j] = acc[i][j];
        }
    }
}

extern "C" void kernel_launch(void* const* d_in, const int* in_sizes, int n_in,
                              void* d_out, int out_size)
{
    (void)in_sizes; (void)n_in; (void)out_size;
    const float* in = (const float*)d_in[0];
    const float* w  = (const float*)d_in[1];
    float* out      = (float*)d_out;

    dim3 grid(31, 32, 2);   // oh pairs (62/2), images, out-channel blocks (256/128)
    conv3x3_kernel<<<grid, 256>>>(in, w, out);
}

// round 4
// speedup vs baseline: 2.3039x; 2.3039x over previous
#include <cuda_runtime.h>
#include <cuda_bf16.h>
#include <cstdint>

// 3x3 valid conv via implicit GEMM on mma.sync.m16n8k16 (bf16, f32 accum),
// bf16 hi/lo 3-term split for fp32-level accuracy.
// NOTE: harness builds for base sm_103 target (no 'a') -> tcgen05 unavailable;
// portable mma.sync is the fastest tensor path this build can emit.
//
// in : [32,128,64,64] f32   w: [256,128,3,3] f32   out: [32,256,62,62] f32
// prep_w : -> [9 taps][256 oc][128 c] bf16 hi/lo
// prep_in: -> [32 n][64 h][64 w][128 c] bf16 hi/lo (NHWC)
// main   : CTA = 128 M (2 oh x 64 ow) x 128 oc; 8 warps of 64x32;
//          K = 9 taps x 128 c, c chunked by 64. Tap shift = linear A-row offset.

#define SW128(o) ((o) ^ (((o) >> 3) & 0x70))

static __device__ __nv_bfloat16 g_in_hi[32 * 64 * 64 * 128];
static __device__ __nv_bfloat16 g_in_lo[32 * 64 * 64 * 128];
static __device__ __nv_bfloat16 g_w_hi[9 * 256 * 128];
static __device__ __nv_bfloat16 g_w_lo[9 * 256 * 128];

// ---------- helpers ----------
__device__ __forceinline__ uint32_t smem_u32(const void* p) {
    uint32_t a;
    asm("{ .reg .u64 t; cvta.to.shared.u64 t, %1; cvt.u32.u64 %0, t; }" : "=r"(a) : "l"(p));
    return a;
}
__device__ __forceinline__ uint32_t lds32(uint32_t a) {
    uint32_t v;
    asm volatile("ld.shared.b32 %0, [%1];" : "=r"(v) : "r"(a));
    return v;
}
__device__ __forceinline__ void sts128(uint32_t a, uint4 v) {
    asm volatile("st.shared.v4.b32 [%0], {%1,%2,%3,%4};" :: "r"(a), "r"(v.x), "r"(v.y), "r"(v.z), "r"(v.w) : "memory");
}
__device__ __forceinline__ void mma16816(float* c, const uint32_t* a, const uint32_t* b) {
    asm volatile("mma.sync.aligned.m16n8k16.row.col.f32.bf16.bf16.f32 "
        "{%0,%1,%2,%3}, {%4,%5,%6,%7}, {%8,%9}, {%0,%1,%2,%3};"
        : "+f"(c[0]), "+f"(c[1]), "+f"(c[2]), "+f"(c[3])
        : "r"(a[0]), "r"(a[1]), "r"(a[2]), "r"(a[3]), "r"(b[0]), "r"(b[1]));
}

// ---------- prep ----------
__device__ __forceinline__ void split_bf16(float v, __nv_bfloat16& hi, __nv_bfloat16& lo) {
    hi = __float2bfloat16(v);
    lo = __float2bfloat16(v - __bfloat162float(hi));
}

__global__ void prep_w_kernel(const float* __restrict__ w) {
    int oc = blockIdx.x, c = threadIdx.x;
    const float* src = w + (oc * 128 + c) * 9;
#pragma unroll
    for (int i = 0; i < 9; i++) {
        __nv_bfloat16 hi, lo;
        split_bf16(src[i], hi, lo);
        int d = (i * 256 + oc) * 128 + c;
        g_w_hi[d] = hi;
        g_w_lo[d] = lo;
    }
}

__global__ void prep_in_kernel(const float* __restrict__ in) {
    __shared__ float tile[128][65];
    int h = blockIdx.x, n = blockIdx.y, tid = threadIdx.x;
    for (int i = tid; i < 8192; i += 256) {
        int c = i >> 6, ww = i & 63;
        tile[c][ww] = in[((n * 128 + c) * 64 + h) * 64 + ww];
    }
    __syncthreads();
    for (int i = tid; i < 8192; i += 256) {
        int ww = i >> 7, c = i & 127;
        __nv_bfloat16 hi, lo;
        split_bf16(tile[c][ww], hi, lo);
        int d = ((n * 64 + h) * 64 + ww) * 128 + c;
        g_in_hi[d] = hi;
        g_in_lo[d] = lo;
    }
}

// ---------- main ----------
// SMEM (bytes): A_hi [264 rows x 128B] (256 staged + pad for tap over-read),
//               A_lo same, B_hi [128 x 128B], B_lo same.
static constexpr int OFF_A_HI = 0;
static constexpr int OFF_A_LO = 264 * 128;            // 33792
static constexpr int OFF_B_HI = 2 * 264 * 128;        // 67584
static constexpr int OFF_B_LO = OFF_B_HI + 128 * 128; // 83968
static constexpr int SMEM_TOTAL = OFF_B_LO + 128 * 128; // 100352 (98KB) -> 2 CTAs/SM

__global__ __launch_bounds__(256, 2) void conv_main(float* __restrict__ out) {
    extern __shared__ char smem[];
    const uint32_t sb = smem_u32(smem);
    const int tid = threadIdx.x;
    const int wid = tid >> 5, lane = tid & 31;
    const int g = lane >> 2, tg = lane & 3;       // mma fragment coords
    const int wy = wid >> 2, wx = wid & 3;        // warp tile: 64M x 32N
    const int oh0 = blockIdx.x * 2;
    const int n = blockIdx.y;
    const int ocb = blockIdx.z;                   // 0/1 -> oc block of 128

    float acc[4][4][4];
#pragma unroll
    for (int i = 0; i < 4; i++)
#pragma unroll
        for (int j = 0; j < 4; j++)
#pragma unroll
            for (int k = 0; k < 4; k++) acc[i][j][k] = 0.0f;

    const uint4* inHi4 = reinterpret_cast<const uint4*>(g_in_hi);
    const uint4* inLo4 = reinterpret_cast<const uint4*>(g_in_lo);
    const uint4* wHi4 = reinterpret_cast<const uint4*>(g_w_hi);
    const uint4* wLo4 = reinterpret_cast<const uint4*>(g_w_lo);

    const uint32_t aHiB = sb + OFF_A_HI, aLoB = sb + OFF_A_LO;
    const uint32_t bHiB = sb + OFF_B_HI, bLoB = sb + OFF_B_LO;

    for (int c0i = 0; c0i < 2; c0i++) {
        const int c0e = c0i * 8;   // chunk offset in uint4 (8 bf16) units
        __syncthreads();           // protect A buffer from previous chunk's readers
        // ---- stage A: 256 rows (4 h x 64 ow) x 64 c, hi+lo; 2048 uint4 each
        for (int i = tid; i < 2048; i += 256) {
            int row = i >> 3, seg = i & 7;
            int gi = ((n * 64 + oh0 + (row >> 6)) * 64 + (row & 63)) * 16 + c0e + seg;
            uint32_t off = SW128(row * 128 + seg * 16);
            sts128(aHiB + off, inHi4[gi]);
            sts128(aLoB + off, inLo4[gi]);
        }
        for (int tap = 0; tap < 9; tap++) {
            if (tap > 0) __syncthreads();  // B readers of previous tap done
            // ---- stage B: 128 oc x 64 c, hi+lo; 1024 uint4 each
            for (int i = tid; i < 1024; i += 256) {
                int oc = i >> 3, seg = i & 7;
                int gi = (tap * 256 + ocb * 128 + oc) * 16 + c0e + seg;
                uint32_t off = SW128(oc * 128 + seg * 16);
                sts128(bHiB + off, wHi4[gi]);
                sts128(bLoB + off, wLo4[gi]);
            }
            __syncthreads();

            const int r = tap / 3, s = tap - r * 3;
            // A row for fragment (i, a1/a3): (wy+r)*64 + s + i*16 + g (+8)
            const uint32_t aRowBase = (uint32_t)(((wy + r) * 64 + s + g) * 128 + tg * 4);
            const uint32_t aXor = (uint32_t)(((s + g) & 7) << 4);
            const uint32_t bRowBase = (uint32_t)((wx * 32 + g) * 128 + tg * 4);
            const uint32_t bXor = (uint32_t)(g << 4);

#pragma unroll
            for (int kk = 0; kk < 4; kk++) {
                const uint32_t ko = (uint32_t)(kk * 32);
                uint32_t ah[4][4], bh[4][2];
#pragma unroll
                for (int i = 0; i < 4; i++) {
                    uint32_t base = aRowBase + (uint32_t)(i * 2048) + ko;
                    ah[i][0] = lds32(aHiB + ((base) ^ aXor));
                    ah[i][1] = lds32(aHiB + ((base + 1024) ^ aXor));
                    ah[i][2] = lds32(aHiB + ((base + 16) ^ aXor));
                    ah[i][3] = lds32(aHiB + ((base + 1040) ^ aXor));
                }
#pragma unroll
                for (int j = 0; j < 4; j++) {
                    uint32_t bb = bRowBase + (uint32_t)(j * 1024) + ko;
                    bh[j][0] = lds32(bHiB + (bb ^ bXor));
                    bh[j][1] = lds32(bHiB + ((bb + 16) ^ bXor));
                }
                // term 1: ah * bh
#pragma unroll
                for (int i = 0; i < 4; i++)
#pragma unroll
                    for (int j = 0; j < 4; j++) mma16816(acc[i][j], ah[i], bh[j]);
                // term 2: al * bh
                {
                    uint32_t al[4][4];
#pragma unroll
                    for (int i = 0; i < 4; i++) {
                        uint32_t base = aRowBase + (uint32_t)(i * 2048) + ko;
                        al[i][0] = lds32(aLoB + ((base) ^ aXor));
                        al[i][1] = lds32(aLoB + ((base + 1024) ^ aXor));
                        al[i][2] = lds32(aLoB + ((base + 16) ^ aXor));
                        al[i][3] = lds32(aLoB + ((base + 1040) ^ aXor));
                    }
#pragma unroll
                    for (int i = 0; i < 4; i++)
#pragma unroll
                        for (int j = 0; j < 4; j++) mma16816(acc[i][j], al[i], bh[j]);
                }
                // term 3: ah * bl
                {
                    uint32_t bl[4][2];
#pragma unroll
                    for (int j = 0; j < 4; j++) {
                        uint32_t bb = bRowBase + (uint32_t)(j * 1024) + ko;
                        bl[j][0] = lds32(bLoB + (bb ^ bXor));
                        bl[j][1] = lds32(bLoB + ((bb + 16) ^ bXor));
                    }
#pragma unroll
                    for (int i = 0; i < 4; i++)
#pragma unroll
                        for (int j = 0; j < 4; j++) mma16816(acc[i][j], ah[i], bl[j]);
                }
            }
        }
    }

    // ---- epilogue ----
    const int oh = oh0 + wy;   // always < 62
#pragma unroll
    for (int i = 0; i < 4; i++) {
        const int ow0 = i * 16 + g;
#pragma unroll
        for (int j = 0; j < 4; j++) {
            const int oc = ocb * 128 + wx * 32 + j * 8 + tg * 2;
            float* op = out + (((size_t)n * 256 + oc) * 62 + oh) * 62;
            if (ow0 < 62) {
                op[ow0] = acc[i][j][0];
                op[3844 + ow0] = acc[i][j][1];
            }
            if (ow0 + 8 < 62) {
                op[ow0 + 8] = acc[i][j][2];
                op[3844 + ow0 + 8] = acc[i][j][3];
            }
        }
    }
}

// ---------- launch ----------
extern "C" void kernel_launch(void* const* d_in, const int* in_sizes, int n_in,
                              void* d_out, int out_size)
{
    (void)in_sizes; (void)n_in; (void)out_size;
    const float* in = (const float*)d_in[0];
    const float* w = (const float*)d_in[1];
    float* out = (float*)d_out;

    cudaFuncSetAttribute(conv_main, cudaFuncAttributeMaxDynamicSharedMemorySize, SMEM_TOTAL);

    prep_w_kernel<<<256, 128>>>(w);
    prep_in_kernel<<<dim3(64, 32), 256>>>(in);
    conv_main<<<dim3(31, 32, 2), 256, SMEM_TOTAL>>>(out);
}